// round 2
// baseline (speedup 1.0000x reference)
#include <cuda_runtime.h>
#include <cstdint>

// Problem dims (fixed by the dataset)
#define M_DIM 8192   // B*S = 4*2048
#define K_DIM 2048   // D_IN
#define N_DIM 8192   // D_OUT

// GEMM tiling
#define BM 128
#define BN 128
#define BK 32
#define LDSS 36            // smem row stride (floats), 32 + 4 pad -> conflict-free frags
#define NKT (K_DIM / BK)   // 64 k-tiles

// Scratch (allocation-free rule: __device__ globals)
__device__ float g_Wt[(size_t)N_DIM * K_DIM];   // ternary weight {-1,0,1} as fp32 (exact in tf32)
__device__ float g_scale[N_DIM];                // per-output-row scale
__device__ float g_Xc[(size_t)M_DIM * K_DIM];   // x rounded to tf32 (cvt.rna)

// ---------------------------------------------------------------------------
// Kernel 1: per-row weight quantization.  scale = max(mean|w|, 1e-5),
// t = clamp(rint(w/scale), -1, 1)  (rint = round-half-even, matches jnp.round)
// ---------------------------------------------------------------------------
__global__ __launch_bounds__(256) void quant_w_kernel(const float* __restrict__ w) {
    const int row  = blockIdx.x;
    const int tid  = threadIdx.x;
    const int lane = tid & 31, warp = tid >> 5;

    const float4* wr = reinterpret_cast<const float4*>(w + (size_t)row * K_DIM);
    float4 v0 = wr[tid];
    float4 v1 = wr[tid + 256];

    float s = fabsf(v0.x) + fabsf(v0.y) + fabsf(v0.z) + fabsf(v0.w)
            + fabsf(v1.x) + fabsf(v1.y) + fabsf(v1.z) + fabsf(v1.w);
    #pragma unroll
    for (int o = 16; o > 0; o >>= 1) s += __shfl_xor_sync(0xffffffffu, s, o);

    __shared__ float red[8];
    __shared__ float sc_sh;
    if (lane == 0) red[warp] = s;
    __syncthreads();
    if (tid == 0) {
        float tot = 0.f;
        #pragma unroll
        for (int i = 0; i < 8; i++) tot += red[i];
        sc_sh = fmaxf(tot * (1.0f / (float)K_DIM), 1e-5f);
    }
    __syncthreads();
    const float sc = sc_sh;

    // IEEE division to match the reference (robust to fast-math flags)
    float q[8];
    q[0]=__fdiv_rn(v0.x,sc); q[1]=__fdiv_rn(v0.y,sc); q[2]=__fdiv_rn(v0.z,sc); q[3]=__fdiv_rn(v0.w,sc);
    q[4]=__fdiv_rn(v1.x,sc); q[5]=__fdiv_rn(v1.y,sc); q[6]=__fdiv_rn(v1.z,sc); q[7]=__fdiv_rn(v1.w,sc);
    #pragma unroll
    for (int i = 0; i < 8; i++) q[i] = fminf(fmaxf(rintf(q[i]), -1.f), 1.f);

    float4* dst = reinterpret_cast<float4*>(g_Wt + (size_t)row * K_DIM);
    dst[tid]       = make_float4(q[0], q[1], q[2], q[3]);
    dst[tid + 256] = make_float4(q[4], q[5], q[6], q[7]);

    if (tid == 0) g_scale[row] = sc;
}

// ---------------------------------------------------------------------------
// Kernel 2: round x to tf32 once (keeps cvt out of the GEMM inner loop)
// ---------------------------------------------------------------------------
__device__ __forceinline__ float to_tf32(float f) {
    uint32_t u;
    asm("cvt.rna.tf32.f32 %0, %1;" : "=r"(u) : "f"(f));
    return __uint_as_float(u);
}

__global__ __launch_bounds__(256) void conv_x_kernel(const float* __restrict__ x) {
    size_t i = (size_t)blockIdx.x * 256 + threadIdx.x;  // one float4 per thread
    float4 v = reinterpret_cast<const float4*>(x)[i];
    v.x = to_tf32(v.x); v.y = to_tf32(v.y); v.z = to_tf32(v.z); v.w = to_tf32(v.w);
    reinterpret_cast<float4*>(g_Xc)[i] = v;
}

// ---------------------------------------------------------------------------
// Kernel 3: TF32 tensor-core GEMM.  C[m,n] = scale[n] * sum_k Xc[m,k]*Wt[n,k]
// Block 128x128x32, 256 threads (8 warps: 2x4 grid, warp tile 64x32),
// cp.async double buffer, mma.sync.m16n8k8.tf32.
// ---------------------------------------------------------------------------
__device__ __forceinline__ uint32_t smem_u32(const void* p) {
    return (uint32_t)__cvta_generic_to_shared(p);
}
__device__ __forceinline__ void cp16(uint32_t dst, const void* src) {
    asm volatile("cp.async.cg.shared.global [%0], [%1], 16;\n" :: "r"(dst), "l"(src));
}

__global__ __launch_bounds__(256, 2) void gemm_tf32_kernel(float* __restrict__ C) {
    extern __shared__ float sm[];
    float* As = sm;                       // [2][BM*LDSS]
    float* Bs = sm + 2 * BM * LDSS;       // [2][BN*LDSS]

    // CTA swizzle: groups of 8 block-rows, walk N inside a group (L2 reuse)
    const int GRID_N = N_DIM / BN;        // 64
    const int GROUP  = 8;
    const int nig    = GROUP * GRID_N;    // 512
    const int bid    = blockIdx.x;
    const int bm     = (bid / nig) * GROUP + (bid % nig) % GROUP;
    const int bn     = (bid % nig) / GROUP;

    const int tid  = threadIdx.x;
    const int lane = tid & 31;
    const int warp = tid >> 5;
    const int wrow = warp >> 2;           // 0..1  (M)
    const int wcol = warp & 3;            // 0..3  (N)
    const int grp  = lane >> 2;           // 0..7
    const int t4   = lane & 3;            // 0..3

    const float* Ag = g_Xc + (size_t)(bm * BM) * K_DIM;
    const float* Bg = g_Wt + (size_t)(bn * BN) * K_DIM;

    float acc[4][4][4];
    #pragma unroll
    for (int a = 0; a < 4; a++)
        #pragma unroll
        for (int b = 0; b < 4; b++)
            #pragma unroll
            for (int c = 0; c < 4; c++) acc[a][b][c] = 0.f;

    // --- stage loader: 4 x 16B for A, 4 x 16B for B per thread ---
    auto load_stage = [&](int kt, int s) {
        float* as = As + s * BM * LDSS;
        float* bs = Bs + s * BM * LDSS;
        #pragma unroll
        for (int i = 0; i < 4; i++) {
            int flat = tid + 256 * i;          // 0..1023
            int row  = flat >> 3;              // 0..127
            int seg  = flat & 7;               // 0..7 (16B segments)
            cp16(smem_u32(as + row * LDSS + seg * 4),
                 Ag + (size_t)row * K_DIM + kt * BK + seg * 4);
            cp16(smem_u32(bs + row * LDSS + seg * 4),
                 Bg + (size_t)row * K_DIM + kt * BK + seg * 4);
        }
        asm volatile("cp.async.commit_group;\n" ::: "memory");
    };

    auto compute = [&](int s) {
        const float* as = As + s * BM * LDSS;
        const float* bs = Bs + s * BM * LDSS;
        #pragma unroll
        for (int ks = 0; ks < 4; ks++) {
            uint32_t af[4][4], bf[4][2];
            const int c = ks * 8 + t4;
            #pragma unroll
            for (int mt = 0; mt < 4; mt++) {
                const int r = wrow * 64 + mt * 16 + grp;
                af[mt][0] = __float_as_uint(as[r * LDSS + c]);
                af[mt][1] = __float_as_uint(as[(r + 8) * LDSS + c]);
                af[mt][2] = __float_as_uint(as[r * LDSS + c + 4]);
                af[mt][3] = __float_as_uint(as[(r + 8) * LDSS + c + 4]);
            }
            #pragma unroll
            for (int nt = 0; nt < 4; nt++) {
                const int n = wcol * 32 + nt * 8 + grp;
                bf[nt][0] = __float_as_uint(bs[n * LDSS + c]);
                bf[nt][1] = __float_as_uint(bs[n * LDSS + c + 4]);
            }
            #pragma unroll
            for (int mt = 0; mt < 4; mt++)
                #pragma unroll
                for (int nt = 0; nt < 4; nt++) {
                    asm volatile(
                        "mma.sync.aligned.m16n8k8.row.col.f32.tf32.tf32.f32 "
                        "{%0,%1,%2,%3}, {%4,%5,%6,%7}, {%8,%9}, {%0,%1,%2,%3};\n"
                        : "+f"(acc[mt][nt][0]), "+f"(acc[mt][nt][1]),
                          "+f"(acc[mt][nt][2]), "+f"(acc[mt][nt][3])
                        : "r"(af[mt][0]), "r"(af[mt][1]), "r"(af[mt][2]), "r"(af[mt][3]),
                          "r"(bf[nt][0]), "r"(bf[nt][1]));
                }
        }
    };

    load_stage(0, 0);
    #pragma unroll 1
    for (int kt = 0; kt < NKT; kt++) {
        if (kt + 1 < NKT) {
            load_stage(kt + 1, (kt + 1) & 1);
            asm volatile("cp.async.wait_group 1;\n" ::: "memory");
        } else {
            asm volatile("cp.async.wait_group 0;\n" ::: "memory");
        }
        __syncthreads();
        compute(kt & 1);
        __syncthreads();
    }

    // Epilogue: apply per-column scale, store fp32
    #pragma unroll
    for (int mt = 0; mt < 4; mt++) {
        const int r0 = bm * BM + wrow * 64 + mt * 16 + grp;
        #pragma unroll
        for (int nt = 0; nt < 4; nt++) {
            const int n0 = bn * BN + wcol * 32 + nt * 8 + 2 * t4;
            const float s0 = __ldg(g_scale + n0);
            const float s1 = __ldg(g_scale + n0 + 1);
            float2 v0 = make_float2(acc[mt][nt][0] * s0, acc[mt][nt][1] * s1);
            float2 v1 = make_float2(acc[mt][nt][2] * s0, acc[mt][nt][3] * s1);
            *reinterpret_cast<float2*>(C + (size_t)r0 * N_DIM + n0)       = v0;
            *reinterpret_cast<float2*>(C + (size_t)(r0 + 8) * N_DIM + n0) = v1;
        }
    }
}

// ---------------------------------------------------------------------------
extern "C" void kernel_launch(void* const* d_in, const int* in_sizes, int n_in,
                              void* d_out, int out_size) {
    (void)in_sizes; (void)n_in; (void)out_size;
    const float* x = (const float*)d_in[0];   // [4,2048,2048]
    const float* w = (const float*)d_in[1];   // [8192,2048]
    float* out = (float*)d_out;               // [4,2048,8192]

    // weight quantize: one block per output row
    quant_w_kernel<<<N_DIM, 256>>>(w);

    // x -> tf32 rounding: 16,777,216 elems / 4 per thread / 256 per block
    conv_x_kernel<<<(M_DIM * (size_t)K_DIM) / 4 / 256, 256>>>(x);

    // GEMM
    const int smem_bytes = 2 * (BM + BN) * LDSS * (int)sizeof(float); // 73728
    cudaFuncSetAttribute(gemm_tf32_kernel,
                         cudaFuncAttributeMaxDynamicSharedMemorySize, smem_bytes);
    gemm_tf32_kernel<<<(M_DIM / BM) * (N_DIM / BN), 256, smem_bytes>>>(out);
}

// round 4
// speedup vs baseline: 2.2260x; 2.2260x over previous
#include <cuda_runtime.h>
#include <cuda_fp16.h>
#include <cstdint>

// Problem dims (fixed by dataset)
#define M_DIM 8192
#define K_DIM 2048
#define N_DIM 8192

// GEMM tiling
#define BM 128
#define BN 256
#define BK 64                 // halves per k-slice = 128 bytes per row
#define NKT (K_DIM / BK)      // 32
#define NSTAGE 4
#define A_BYTES (BM * 128)    // 16384
#define B_BYTES (BN * 128)    // 32768
#define STAGE_BYTES (A_BYTES + B_BYTES)            // 49152
#define SMEM_TOTAL (NSTAGE * STAGE_BYTES)          // 196608

// Scratch (allocation-free rule: __device__ globals)
__device__ __half g_Xh[(size_t)M_DIM * K_DIM];
__device__ __half g_Wq[(size_t)N_DIM * K_DIM];
__device__ float  g_scale[N_DIM];

// ---------------------------------------------------------------------------
__device__ __forceinline__ uint32_t smem_u32(const void* p) {
    return (uint32_t)__cvta_generic_to_shared(p);
}
__device__ __forceinline__ void cp16(uint32_t dst, const void* src) {
    asm volatile("cp.async.cg.shared.global [%0], [%1], 16;\n" :: "r"(dst), "l"(src));
}
__device__ __forceinline__ void ldsm_x4(uint32_t& r0, uint32_t& r1, uint32_t& r2,
                                        uint32_t& r3, uint32_t addr) {
    asm volatile("ldmatrix.sync.aligned.m8n8.x4.shared.b16 {%0,%1,%2,%3}, [%4];"
                 : "=r"(r0), "=r"(r1), "=r"(r2), "=r"(r3) : "r"(addr));
}
__device__ __forceinline__ uint2 pack4_h(float a, float b, float c, float d) {
    __half2 p0 = __floats2half2_rn(a, b);
    __half2 p1 = __floats2half2_rn(c, d);
    uint2 r;
    r.x = *reinterpret_cast<uint32_t*>(&p0);
    r.y = *reinterpret_cast<uint32_t*>(&p1);
    return r;
}

// ---------------------------------------------------------------------------
// Kernel 1: per-row weight quantization -> ternary fp16 + fp32 scale
// ---------------------------------------------------------------------------
__global__ __launch_bounds__(256) void quant_w_kernel(const float* __restrict__ w) {
    const int row  = blockIdx.x;
    const int tid  = threadIdx.x;
    const int lane = tid & 31, warp = tid >> 5;

    const float4* wr = reinterpret_cast<const float4*>(w + (size_t)row * K_DIM);
    float4 v0 = wr[tid];
    float4 v1 = wr[tid + 256];

    float s = fabsf(v0.x)+fabsf(v0.y)+fabsf(v0.z)+fabsf(v0.w)
            + fabsf(v1.x)+fabsf(v1.y)+fabsf(v1.z)+fabsf(v1.w);
    #pragma unroll
    for (int o = 16; o > 0; o >>= 1) s += __shfl_xor_sync(0xffffffffu, s, o);

    __shared__ float red[8];
    __shared__ float sc_sh;
    if (lane == 0) red[warp] = s;
    __syncthreads();
    if (tid == 0) {
        float tot = 0.f;
        #pragma unroll
        for (int i = 0; i < 8; i++) tot += red[i];
        sc_sh = fmaxf(tot * (1.0f / (float)K_DIM), 1e-5f);
    }
    __syncthreads();
    const float sc = sc_sh;

    float q[8];
    q[0]=__fdiv_rn(v0.x,sc); q[1]=__fdiv_rn(v0.y,sc); q[2]=__fdiv_rn(v0.z,sc); q[3]=__fdiv_rn(v0.w,sc);
    q[4]=__fdiv_rn(v1.x,sc); q[5]=__fdiv_rn(v1.y,sc); q[6]=__fdiv_rn(v1.z,sc); q[7]=__fdiv_rn(v1.w,sc);
    #pragma unroll
    for (int i = 0; i < 8; i++) q[i] = fminf(fmaxf(rintf(q[i]), -1.f), 1.f);

    uint2* dst = reinterpret_cast<uint2*>(g_Wq + (size_t)row * K_DIM);
    dst[tid]       = pack4_h(q[0], q[1], q[2], q[3]);
    dst[tid + 256] = pack4_h(q[4], q[5], q[6], q[7]);

    if (tid == 0) g_scale[row] = sc;
}

// ---------------------------------------------------------------------------
// Kernel 2: x -> fp16
// ---------------------------------------------------------------------------
__global__ __launch_bounds__(256) void conv_x_kernel(const float* __restrict__ x) {
    size_t i = (size_t)blockIdx.x * 256 + threadIdx.x;   // one float4 per thread
    float4 v = reinterpret_cast<const float4*>(x)[i];
    reinterpret_cast<uint2*>(g_Xh)[i] = pack4_h(v.x, v.y, v.z, v.w);
}

// ---------------------------------------------------------------------------
// Kernel 3: fp16 HMMA GEMM.  C[m,n] = scale[n] * sum_k Xh[m,k]*Wq[n,k]
// 128x256x64 tile, 256 thr (8 warps 2x4, warp tile 64x64), 4-stage cp.async,
// XOR-swizzled smem + ldmatrix.x4 fragments, mma.sync.m16n8k16.f16 (fp32 acc)
// ---------------------------------------------------------------------------
__global__ __launch_bounds__(256, 1) void gemm_f16_kernel(float* __restrict__ C) {
    extern __shared__ char smem[];
    const uint32_t sbase = smem_u32(smem);

    const int tid  = threadIdx.x;
    const int lane = tid & 31;
    const int warp = tid >> 5;
    const int wrow = warp >> 2;           // 0..1 (M, 64 each)
    const int wcol = warp & 3;            // 0..3 (N, 64 each)

    // CTA swizzle: GROUP=8 along M, walk all N inside a group (L2 reuse)
    const int GRID_N = N_DIM / BN;        // 32
    const int GROUP  = 8;
    const int nig    = GROUP * GRID_N;    // 256
    const int bid    = blockIdx.x;
    const int bm     = (bid / nig) * GROUP + (bid % nig) % GROUP;
    const int bn     = (bid % nig) / GROUP;

    const __half* Ag = g_Xh + (size_t)(bm * BM) * K_DIM;
    const __half* Bg = g_Wq + (size_t)(bn * BN) * K_DIM;

    // ldmatrix per-lane row/seg decomposition (row%8 == lane%8 in all cases)
    const int a_row = (lane & 7) + ((lane >> 3) & 1) * 8;   // 0..15
    const int a_sh  = lane >> 4;                            // k-seg half 0/1
    const int b_row = (lane & 7) + (lane >> 4) * 8;         // 0..15
    const int b_sh  = (lane >> 3) & 1;
    const int lxor  = lane & 7;

    float acc[4][8][4];
    #pragma unroll
    for (int a = 0; a < 4; a++)
        #pragma unroll
        for (int b = 0; b < 8; b++)
            #pragma unroll
            for (int c = 0; c < 4; c++) acc[a][b][c] = 0.f;

    // --- stage loader: 12 x 16B per thread (A:4, B:8) ---
    auto load_stage = [&](int kt, int s) {
        const uint32_t st = sbase + s * STAGE_BYTES;
        const int kof = kt * BK;
        #pragma unroll
        for (int i = 0; i < 4; i++) {                 // A: 1024 16B chunks
            int flat = tid + 256 * i;
            int row = flat >> 3, seg = flat & 7;
            cp16(st + row * 128 + ((seg ^ (row & 7)) << 4),
                 Ag + (size_t)row * K_DIM + kof + seg * 8);
        }
        #pragma unroll
        for (int i = 0; i < 8; i++) {                 // B: 2048 16B chunks
            int flat = tid + 256 * i;
            int row = flat >> 3, seg = flat & 7;
            cp16(st + A_BYTES + row * 128 + ((seg ^ (row & 7)) << 4),
                 Bg + (size_t)row * K_DIM + kof + seg * 8);
        }
    };

    auto compute = [&](int s) {
        const uint32_t aB = sbase + s * STAGE_BYTES;
        const uint32_t bB = aB + A_BYTES;
        #pragma unroll
        for (int ks = 0; ks < 4; ks++) {
            uint32_t af[4][4], bf[4][4];
            #pragma unroll
            for (int mt = 0; mt < 4; mt++) {
                const int row = wrow * 64 + mt * 16 + a_row;
                const int seg = 2 * ks + a_sh;
                ldsm_x4(af[mt][0], af[mt][1], af[mt][2], af[mt][3],
                        aB + row * 128 + ((seg ^ lxor) << 4));
            }
            #pragma unroll
            for (int nt = 0; nt < 4; nt++) {
                const int row = wcol * 64 + nt * 16 + b_row;
                const int seg = 2 * ks + b_sh;
                ldsm_x4(bf[nt][0], bf[nt][1], bf[nt][2], bf[nt][3],
                        bB + row * 128 + ((seg ^ lxor) << 4));
            }
            #pragma unroll
            for (int mt = 0; mt < 4; mt++)
                #pragma unroll
                for (int nt = 0; nt < 4; nt++) {
                    asm volatile(
                        "mma.sync.aligned.m16n8k16.row.col.f32.f16.f16.f32 "
                        "{%0,%1,%2,%3}, {%4,%5,%6,%7}, {%8,%9}, {%0,%1,%2,%3};\n"
                        : "+f"(acc[mt][2*nt][0]), "+f"(acc[mt][2*nt][1]),
                          "+f"(acc[mt][2*nt][2]), "+f"(acc[mt][2*nt][3])
                        : "r"(af[mt][0]), "r"(af[mt][1]), "r"(af[mt][2]), "r"(af[mt][3]),
                          "r"(bf[nt][0]), "r"(bf[nt][1]));
                    asm volatile(
                        "mma.sync.aligned.m16n8k16.row.col.f32.f16.f16.f32 "
                        "{%0,%1,%2,%3}, {%4,%5,%6,%7}, {%8,%9}, {%0,%1,%2,%3};\n"
                        : "+f"(acc[mt][2*nt+1][0]), "+f"(acc[mt][2*nt+1][1]),
                          "+f"(acc[mt][2*nt+1][2]), "+f"(acc[mt][2*nt+1][3])
                        : "r"(af[mt][0]), "r"(af[mt][1]), "r"(af[mt][2]), "r"(af[mt][3]),
                          "r"(bf[nt][2]), "r"(bf[nt][3]));
                }
        }
    };

    // prologue: stages 0..2
    #pragma unroll
    for (int j = 0; j < NSTAGE - 1; j++) {
        load_stage(j, j);
        asm volatile("cp.async.commit_group;\n" ::: "memory");
    }

    #pragma unroll 1
    for (int kt = 0; kt < NKT; kt++) {
        const int j = kt + NSTAGE - 1;
        if (j < NKT) load_stage(j, j % NSTAGE);
        asm volatile("cp.async.commit_group;\n" ::: "memory");   // keeps group count uniform
        asm volatile("cp.async.wait_group %0;\n" :: "n"(NSTAGE - 1) : "memory");
        __syncthreads();
        compute(kt % NSTAGE);
        __syncthreads();
    }

    // ---- epilogue: per-column scale, fp32 stores ----
    const int l4r = lane >> 2;            // 0..7
    const int l4c = lane & 3;             // 0..3
    #pragma unroll
    for (int mt = 0; mt < 4; mt++) {
        const int r0 = bm * BM + wrow * 64 + mt * 16 + l4r;
        #pragma unroll
        for (int nt = 0; nt < 8; nt++) {
            const int n0 = bn * BN + wcol * 64 + nt * 8 + 2 * l4c;
            const float s0 = __ldg(g_scale + n0);
            const float s1 = __ldg(g_scale + n0 + 1);
            float2 v0 = make_float2(acc[mt][nt][0] * s0, acc[mt][nt][1] * s1);
            float2 v1 = make_float2(acc[mt][nt][2] * s0, acc[mt][nt][3] * s1);
            *reinterpret_cast<float2*>(C + (size_t)r0 * N_DIM + n0)       = v0;
            *reinterpret_cast<float2*>(C + (size_t)(r0 + 8) * N_DIM + n0) = v1;
        }
    }
}

// ---------------------------------------------------------------------------
extern "C" void kernel_launch(void* const* d_in, const int* in_sizes, int n_in,
                              void* d_out, int out_size) {
    (void)in_sizes; (void)n_in; (void)out_size;
    const float* x = (const float*)d_in[0];
    const float* w = (const float*)d_in[1];
    float* out = (float*)d_out;

    quant_w_kernel<<<N_DIM, 256>>>(w);
    conv_x_kernel<<<(unsigned)((size_t)M_DIM * K_DIM / 4 / 256), 256>>>(x);

    cudaFuncSetAttribute(gemm_f16_kernel,
                         cudaFuncAttributeMaxDynamicSharedMemorySize, SMEM_TOTAL);
    gemm_f16_kernel<<<(M_DIM / BM) * (N_DIM / BN), 256, SMEM_TOTAL>>>(out);
}

// round 5
// speedup vs baseline: 2.2565x; 1.0137x over previous
#include <cuda_runtime.h>
#include <cuda_fp16.h>
#include <cstdint>

// Problem dims (fixed by dataset)
#define M_DIM 8192
#define K_DIM 2048
#define N_DIM 8192

// GEMM tiling
#define BM 128
#define BN 256
#define BK 64                 // halves per k-slice = 128 bytes per row
#define NKT (K_DIM / BK)      // 32
#define NSTAGE 4
#define A_BYTES (BM * 128)    // 16384
#define B_BYTES (BN * 128)    // 32768
#define STAGE_BYTES (A_BYTES + B_BYTES)            // 49152
#define SMEM_TOTAL (NSTAGE * STAGE_BYTES)          // 196608

// Scratch (allocation-free rule: __device__ globals)
__device__ __half g_Xh[(size_t)M_DIM * K_DIM];
__device__ __half g_Wq[(size_t)N_DIM * K_DIM];
__device__ float  g_scale[N_DIM];

// ---------------------------------------------------------------------------
__device__ __forceinline__ uint32_t smem_u32(const void* p) {
    return (uint32_t)__cvta_generic_to_shared(p);
}
__device__ __forceinline__ void cp16(uint32_t dst, const void* src) {
    asm volatile("cp.async.cg.shared.global [%0], [%1], 16;\n" :: "r"(dst), "l"(src));
}
__device__ __forceinline__ void ldsm_x4(uint32_t& r0, uint32_t& r1, uint32_t& r2,
                                        uint32_t& r3, uint32_t addr) {
    asm volatile("ldmatrix.sync.aligned.m8n8.x4.shared.b16 {%0,%1,%2,%3}, [%4];"
                 : "=r"(r0), "=r"(r1), "=r"(r2), "=r"(r3) : "r"(addr));
}
__device__ __forceinline__ uint2 pack4_h(float a, float b, float c, float d) {
    __half2 p0 = __floats2half2_rn(a, b);
    __half2 p1 = __floats2half2_rn(c, d);
    uint2 r;
    r.x = *reinterpret_cast<uint32_t*>(&p0);
    r.y = *reinterpret_cast<uint32_t*>(&p1);
    return r;
}

// ---------------------------------------------------------------------------
// Kernel 1: per-row weight quantization -> ternary fp16 + fp32 scale
// ---------------------------------------------------------------------------
__global__ __launch_bounds__(256) void quant_w_kernel(const float* __restrict__ w) {
    const int row  = blockIdx.x;
    const int tid  = threadIdx.x;
    const int lane = tid & 31, warp = tid >> 5;

    const float4* wr = reinterpret_cast<const float4*>(w + (size_t)row * K_DIM);
    float4 v0 = wr[tid];
    float4 v1 = wr[tid + 256];

    float s = fabsf(v0.x)+fabsf(v0.y)+fabsf(v0.z)+fabsf(v0.w)
            + fabsf(v1.x)+fabsf(v1.y)+fabsf(v1.z)+fabsf(v1.w);
    #pragma unroll
    for (int o = 16; o > 0; o >>= 1) s += __shfl_xor_sync(0xffffffffu, s, o);

    __shared__ float red[8];
    __shared__ float sc_sh;
    if (lane == 0) red[warp] = s;
    __syncthreads();
    if (tid == 0) {
        float tot = 0.f;
        #pragma unroll
        for (int i = 0; i < 8; i++) tot += red[i];
        sc_sh = fmaxf(tot * (1.0f / (float)K_DIM), 1e-5f);
    }
    __syncthreads();
    const float sc = sc_sh;

    float q[8];
    q[0]=__fdiv_rn(v0.x,sc); q[1]=__fdiv_rn(v0.y,sc); q[2]=__fdiv_rn(v0.z,sc); q[3]=__fdiv_rn(v0.w,sc);
    q[4]=__fdiv_rn(v1.x,sc); q[5]=__fdiv_rn(v1.y,sc); q[6]=__fdiv_rn(v1.z,sc); q[7]=__fdiv_rn(v1.w,sc);
    #pragma unroll
    for (int i = 0; i < 8; i++) q[i] = fminf(fmaxf(rintf(q[i]), -1.f), 1.f);

    uint2* dst = reinterpret_cast<uint2*>(g_Wq + (size_t)row * K_DIM);
    dst[tid]       = pack4_h(q[0], q[1], q[2], q[3]);
    dst[tid + 256] = pack4_h(q[4], q[5], q[6], q[7]);

    if (tid == 0) g_scale[row] = sc;
}

// ---------------------------------------------------------------------------
// Kernel 2: x -> fp16
// ---------------------------------------------------------------------------
__global__ __launch_bounds__(256) void conv_x_kernel(const float* __restrict__ x) {
    size_t i = (size_t)blockIdx.x * 256 + threadIdx.x;   // one float4 per thread
    float4 v = reinterpret_cast<const float4*>(x)[i];
    reinterpret_cast<uint2*>(g_Xh)[i] = pack4_h(v.x, v.y, v.z, v.w);
}

// ---------------------------------------------------------------------------
// Kernel 3: fp16 HMMA GEMM.  C[m,n] = scale[n] * sum_k Xh[m,k]*Wq[n,k]
// 128x256x64 tile, 256 thr (8 warps 2x4, warp tile 64x64), 4-stage cp.async,
// single __syncthreads per k-iter, fragment double-buffer across ks steps.
// ---------------------------------------------------------------------------
__global__ __launch_bounds__(256, 1) void gemm_f16_kernel(float* __restrict__ C) {
    extern __shared__ char smem[];
    const uint32_t sbase = smem_u32(smem);

    const int tid  = threadIdx.x;
    const int lane = tid & 31;
    const int warp = tid >> 5;
    const int wrow = warp >> 2;           // 0..1 (M, 64 each)
    const int wcol = warp & 3;            // 0..3 (N, 64 each)

    // CTA swizzle: GROUP=8 along M, walk all N inside a group (L2 reuse)
    const int GRID_N = N_DIM / BN;        // 32
    const int GROUP  = 8;
    const int nig    = GROUP * GRID_N;    // 256
    const int bid    = blockIdx.x;
    const int bm     = (bid / nig) * GROUP + (bid % nig) % GROUP;
    const int bn     = (bid % nig) / GROUP;

    const __half* Ag = g_Xh + (size_t)(bm * BM) * K_DIM;
    const __half* Bg = g_Wq + (size_t)(bn * BN) * K_DIM;

    // ldmatrix per-lane row/seg decomposition
    const int a_row = (lane & 7) + ((lane >> 3) & 1) * 8;   // 0..15
    const int a_sh  = lane >> 4;                            // k-seg half 0/1
    const int b_row = (lane & 7) + (lane >> 4) * 8;         // 0..15
    const int b_sh  = (lane >> 3) & 1;
    const int lxor  = lane & 7;

    float acc[4][8][4];
    #pragma unroll
    for (int a = 0; a < 4; a++)
        #pragma unroll
        for (int b = 0; b < 8; b++)
            #pragma unroll
            for (int c = 0; c < 4; c++) acc[a][b][c] = 0.f;

    // --- stage loader: 12 x 16B per thread (A:4, B:8) ---
    auto load_stage = [&](int kt, int s) {
        const uint32_t st = sbase + s * STAGE_BYTES;
        const int kof = kt * BK;
        #pragma unroll
        for (int i = 0; i < 4; i++) {                 // A: 1024 16B chunks
            int flat = tid + 256 * i;
            int row = flat >> 3, seg = flat & 7;
            cp16(st + row * 128 + ((seg ^ (row & 7)) << 4),
                 Ag + (size_t)row * K_DIM + kof + seg * 8);
        }
        #pragma unroll
        for (int i = 0; i < 8; i++) {                 // B: 2048 16B chunks
            int flat = tid + 256 * i;
            int row = flat >> 3, seg = flat & 7;
            cp16(st + A_BYTES + row * 128 + ((seg ^ (row & 7)) << 4),
                 Bg + (size_t)row * K_DIM + kof + seg * 8);
        }
    };

    // --- fragment loader for one ks step ---
    auto load_frags = [&](uint32_t aB, uint32_t bB, int ks,
                          uint32_t (*af)[4], uint32_t (*bf)[4]) {
        #pragma unroll
        for (int mt = 0; mt < 4; mt++) {
            const int row = wrow * 64 + mt * 16 + a_row;
            const int seg = 2 * ks + a_sh;
            ldsm_x4(af[mt][0], af[mt][1], af[mt][2], af[mt][3],
                    aB + row * 128 + ((seg ^ lxor) << 4));
        }
        #pragma unroll
        for (int nt = 0; nt < 4; nt++) {
            const int row = wcol * 64 + nt * 16 + b_row;
            const int seg = 2 * ks + b_sh;
            ldsm_x4(bf[nt][0], bf[nt][1], bf[nt][2], bf[nt][3],
                    bB + row * 128 + ((seg ^ lxor) << 4));
        }
    };

    auto mma_step = [&](uint32_t (*af)[4], uint32_t (*bf)[4]) {
        #pragma unroll
        for (int mt = 0; mt < 4; mt++)
            #pragma unroll
            for (int nt = 0; nt < 4; nt++) {
                asm volatile(
                    "mma.sync.aligned.m16n8k16.row.col.f32.f16.f16.f32 "
                    "{%0,%1,%2,%3}, {%4,%5,%6,%7}, {%8,%9}, {%0,%1,%2,%3};\n"
                    : "+f"(acc[mt][2*nt][0]), "+f"(acc[mt][2*nt][1]),
                      "+f"(acc[mt][2*nt][2]), "+f"(acc[mt][2*nt][3])
                    : "r"(af[mt][0]), "r"(af[mt][1]), "r"(af[mt][2]), "r"(af[mt][3]),
                      "r"(bf[nt][0]), "r"(bf[nt][1]));
                asm volatile(
                    "mma.sync.aligned.m16n8k16.row.col.f32.f16.f16.f32 "
                    "{%0,%1,%2,%3}, {%4,%5,%6,%7}, {%8,%9}, {%0,%1,%2,%3};\n"
                    : "+f"(acc[mt][2*nt+1][0]), "+f"(acc[mt][2*nt+1][1]),
                      "+f"(acc[mt][2*nt+1][2]), "+f"(acc[mt][2*nt+1][3])
                    : "r"(af[mt][0]), "r"(af[mt][1]), "r"(af[mt][2]), "r"(af[mt][3]),
                      "r"(bf[nt][2]), "r"(bf[nt][3]));
            }
    };

    // prologue: stages 0..NSTAGE-2
    #pragma unroll
    for (int j = 0; j < NSTAGE - 1; j++) {
        load_stage(j, j);
        asm volatile("cp.async.commit_group;\n" ::: "memory");
    }

    uint32_t af[2][4][4], bf[2][4][4];

    #pragma unroll 1
    for (int kt = 0; kt < NKT; kt++) {
        // stage kt resident for THIS thread...
        asm volatile("cp.async.wait_group %0;\n" :: "n"(NSTAGE - 2) : "memory");
        // ...and for all threads; also: all warps finished compute(kt-1), so the
        // slot that load_stage(kt+NSTAGE-1) writes below (== slot of kt-1) is free.
        __syncthreads();

        const int j = kt + NSTAGE - 1;
        if (j < NKT) load_stage(j, j % NSTAGE);
        asm volatile("cp.async.commit_group;\n" ::: "memory");   // empty group in tail keeps counts uniform

        const uint32_t aB = sbase + (kt % NSTAGE) * STAGE_BYTES;
        const uint32_t bB = aB + A_BYTES;

        load_frags(aB, bB, 0, af[0], bf[0]);
        #pragma unroll
        for (int ks = 0; ks < 4; ks++) {
            if (ks < 3) load_frags(aB, bB, ks + 1, af[(ks + 1) & 1], bf[(ks + 1) & 1]);
            mma_step(af[ks & 1], bf[ks & 1]);
        }
    }

    // ---- epilogue: per-column scale, fp32 stores ----
    const int l4r = lane >> 2;            // 0..7
    const int l4c = lane & 3;             // 0..3
    #pragma unroll
    for (int mt = 0; mt < 4; mt++) {
        const int r0 = bm * BM + wrow * 64 + mt * 16 + l4r;
        #pragma unroll
        for (int nt = 0; nt < 8; nt++) {
            const int n0 = bn * BN + wcol * 64 + nt * 8 + 2 * l4c;
            const float s0 = __ldg(g_scale + n0);
            const float s1 = __ldg(g_scale + n0 + 1);
            float2 v0 = make_float2(acc[mt][nt][0] * s0, acc[mt][nt][1] * s1);
            float2 v1 = make_float2(acc[mt][nt][2] * s0, acc[mt][nt][3] * s1);
            *reinterpret_cast<float2*>(C + (size_t)r0 * N_DIM + n0)       = v0;
            *reinterpret_cast<float2*>(C + (size_t)(r0 + 8) * N_DIM + n0) = v1;
        }
    }
}

// ---------------------------------------------------------------------------
extern "C" void kernel_launch(void* const* d_in, const int* in_sizes, int n_in,
                              void* d_out, int out_size) {
    (void)in_sizes; (void)n_in; (void)out_size;
    const float* x = (const float*)d_in[0];
    const float* w = (const float*)d_in[1];
    float* out = (float*)d_out;

    quant_w_kernel<<<N_DIM, 256>>>(w);
    conv_x_kernel<<<(unsigned)((size_t)M_DIM * K_DIM / 4 / 256), 256>>>(x);

    cudaFuncSetAttribute(gemm_f16_kernel,
                         cudaFuncAttributeMaxDynamicSharedMemorySize, SMEM_TOTAL);
    gemm_f16_kernel<<<(M_DIM / BM) * (N_DIM / BN), 256, SMEM_TOTAL>>>(out);
}

// round 6
// speedup vs baseline: 2.3529x; 1.0427x over previous
#include <cuda_runtime.h>
#include <cuda_fp16.h>
#include <cstdint>

// Problem dims (fixed by dataset)
#define M_DIM 8192
#define K_DIM 2048
#define N_DIM 8192

// GEMM tiling
#define BM 128
#define BN 256
#define BK 64                 // halves per k-slice = 128 bytes per row
#define NKT (K_DIM / BK)      // 32
#define NSTAGE 4
#define NTHREADS 512
#define A_BYTES (BM * 128)    // 16384
#define B_BYTES (BN * 128)    // 32768
#define STAGE_BYTES (A_BYTES + B_BYTES)            // 49152
#define SMEM_TOTAL (NSTAGE * STAGE_BYTES)          // 196608

// Scratch (allocation-free rule: __device__ globals)
__device__ __half g_Xh[(size_t)M_DIM * K_DIM];
__device__ __half g_Wq[(size_t)N_DIM * K_DIM];
__device__ float  g_scale[N_DIM];

// ---------------------------------------------------------------------------
__device__ __forceinline__ uint32_t smem_u32(const void* p) {
    return (uint32_t)__cvta_generic_to_shared(p);
}
__device__ __forceinline__ void cp16(uint32_t dst, const void* src) {
    asm volatile("cp.async.cg.shared.global [%0], [%1], 16;\n" :: "r"(dst), "l"(src));
}
__device__ __forceinline__ void ldsm_x4(uint32_t& r0, uint32_t& r1, uint32_t& r2,
                                        uint32_t& r3, uint32_t addr) {
    asm volatile("ldmatrix.sync.aligned.m8n8.x4.shared.b16 {%0,%1,%2,%3}, [%4];"
                 : "=r"(r0), "=r"(r1), "=r"(r2), "=r"(r3) : "r"(addr));
}
__device__ __forceinline__ uint2 pack4_h(float a, float b, float c, float d) {
    __half2 p0 = __floats2half2_rn(a, b);
    __half2 p1 = __floats2half2_rn(c, d);
    uint2 r;
    r.x = *reinterpret_cast<uint32_t*>(&p0);
    r.y = *reinterpret_cast<uint32_t*>(&p1);
    return r;
}

// ---------------------------------------------------------------------------
// Kernel 1: per-row weight quantization -> ternary fp16 + fp32 scale
// ---------------------------------------------------------------------------
__global__ __launch_bounds__(256) void quant_w_kernel(const float* __restrict__ w) {
    const int row  = blockIdx.x;
    const int tid  = threadIdx.x;
    const int lane = tid & 31, warp = tid >> 5;

    const float4* wr = reinterpret_cast<const float4*>(w + (size_t)row * K_DIM);
    float4 v0 = wr[tid];
    float4 v1 = wr[tid + 256];

    float s = fabsf(v0.x)+fabsf(v0.y)+fabsf(v0.z)+fabsf(v0.w)
            + fabsf(v1.x)+fabsf(v1.y)+fabsf(v1.z)+fabsf(v1.w);
    #pragma unroll
    for (int o = 16; o > 0; o >>= 1) s += __shfl_xor_sync(0xffffffffu, s, o);

    __shared__ float red[8];
    __shared__ float sc_sh;
    if (lane == 0) red[warp] = s;
    __syncthreads();
    if (tid == 0) {
        float tot = 0.f;
        #pragma unroll
        for (int i = 0; i < 8; i++) tot += red[i];
        sc_sh = fmaxf(tot * (1.0f / (float)K_DIM), 1e-5f);
    }
    __syncthreads();
    const float sc = sc_sh;

    float q[8];
    q[0]=__fdiv_rn(v0.x,sc); q[1]=__fdiv_rn(v0.y,sc); q[2]=__fdiv_rn(v0.z,sc); q[3]=__fdiv_rn(v0.w,sc);
    q[4]=__fdiv_rn(v1.x,sc); q[5]=__fdiv_rn(v1.y,sc); q[6]=__fdiv_rn(v1.z,sc); q[7]=__fdiv_rn(v1.w,sc);
    #pragma unroll
    for (int i = 0; i < 8; i++) q[i] = fminf(fmaxf(rintf(q[i]), -1.f), 1.f);

    uint2* dst = reinterpret_cast<uint2*>(g_Wq + (size_t)row * K_DIM);
    dst[tid]       = pack4_h(q[0], q[1], q[2], q[3]);
    dst[tid + 256] = pack4_h(q[4], q[5], q[6], q[7]);

    if (tid == 0) g_scale[row] = sc;
}

// ---------------------------------------------------------------------------
// Kernel 2: x -> fp16
// ---------------------------------------------------------------------------
__global__ __launch_bounds__(256) void conv_x_kernel(const float* __restrict__ x) {
    size_t i = (size_t)blockIdx.x * 256 + threadIdx.x;   // one float4 per thread
    float4 v = reinterpret_cast<const float4*>(x)[i];
    reinterpret_cast<uint2*>(g_Xh)[i] = pack4_h(v.x, v.y, v.z, v.w);
}

// ---------------------------------------------------------------------------
// Kernel 3: fp16 HMMA GEMM.  C[m,n] = scale[n] * sum_k Xh[m,k]*Wq[n,k]
// 128x256x64 tile, 512 thr (16 warps 2x8, warp tile 64x32 -> 4 warps/SMSP),
// 4-stage cp.async, single __syncthreads per k-iter.
// ---------------------------------------------------------------------------
__global__ __launch_bounds__(NTHREADS, 1) void gemm_f16_kernel(float* __restrict__ C) {
    extern __shared__ char smem[];
    const uint32_t sbase = smem_u32(smem);

    const int tid  = threadIdx.x;
    const int lane = tid & 31;
    const int warp = tid >> 5;
    const int wrow = warp >> 3;           // 0..1 (M, 64 each)
    const int wcol = warp & 7;            // 0..7 (N, 32 each)

    // CTA swizzle: GROUP=8 along M, walk all N inside a group (L2 reuse)
    const int GRID_N = N_DIM / BN;        // 32
    const int GROUP  = 8;
    const int nig    = GROUP * GRID_N;    // 256
    const int bid    = blockIdx.x;
    const int bm     = (bid / nig) * GROUP + (bid % nig) % GROUP;
    const int bn     = (bid % nig) / GROUP;

    const __half* Ag = g_Xh + (size_t)(bm * BM) * K_DIM;
    const __half* Bg = g_Wq + (size_t)(bn * BN) * K_DIM;

    // ldmatrix per-lane row/seg decomposition
    const int a_row = (lane & 7) + ((lane >> 3) & 1) * 8;   // 0..15
    const int a_sh  = lane >> 4;                            // k-seg half 0/1
    const int b_row = (lane & 7) + (lane >> 4) * 8;         // 0..15
    const int b_sh  = (lane >> 3) & 1;
    const int lxor  = lane & 7;

    float acc[4][4][4];
    #pragma unroll
    for (int a = 0; a < 4; a++)
        #pragma unroll
        for (int b = 0; b < 4; b++)
            #pragma unroll
            for (int c = 0; c < 4; c++) acc[a][b][c] = 0.f;

    // --- stage loader: 6 x 16B per thread (A:2, B:4) ---
    auto load_stage = [&](int kt, int s) {
        const uint32_t st = sbase + s * STAGE_BYTES;
        const int kof = kt * BK;
        #pragma unroll
        for (int i = 0; i < 2; i++) {                 // A: 1024 16B chunks
            int flat = tid + NTHREADS * i;
            int row = flat >> 3, seg = flat & 7;
            cp16(st + row * 128 + ((seg ^ (row & 7)) << 4),
                 Ag + (size_t)row * K_DIM + kof + seg * 8);
        }
        #pragma unroll
        for (int i = 0; i < 4; i++) {                 // B: 2048 16B chunks
            int flat = tid + NTHREADS * i;
            int row = flat >> 3, seg = flat & 7;
            cp16(st + A_BYTES + row * 128 + ((seg ^ (row & 7)) << 4),
                 Bg + (size_t)row * K_DIM + kof + seg * 8);
        }
    };

    // prologue: stages 0..NSTAGE-2
    #pragma unroll
    for (int j = 0; j < NSTAGE - 1; j++) {
        load_stage(j, j);
        asm volatile("cp.async.commit_group;\n" ::: "memory");
    }

    #pragma unroll 1
    for (int kt = 0; kt < NKT; kt++) {
        asm volatile("cp.async.wait_group %0;\n" :: "n"(NSTAGE - 2) : "memory");
        __syncthreads();   // stage kt visible to all; slot for (kt-1) free for reuse

        const int j = kt + NSTAGE - 1;
        if (j < NKT) load_stage(j, j % NSTAGE);
        asm volatile("cp.async.commit_group;\n" ::: "memory");   // empty group in tail keeps counts uniform

        const uint32_t aB = sbase + (kt % NSTAGE) * STAGE_BYTES;
        const uint32_t bB = aB + A_BYTES;

        #pragma unroll
        for (int ks = 0; ks < 4; ks++) {
            uint32_t af[4][4], bf[2][4];
            #pragma unroll
            for (int mt = 0; mt < 4; mt++) {
                const int row = wrow * 64 + mt * 16 + a_row;
                const int seg = 2 * ks + a_sh;
                ldsm_x4(af[mt][0], af[mt][1], af[mt][2], af[mt][3],
                        aB + row * 128 + ((seg ^ lxor) << 4));
            }
            #pragma unroll
            for (int nt = 0; nt < 2; nt++) {
                const int row = wcol * 32 + nt * 16 + b_row;
                const int seg = 2 * ks + b_sh;
                ldsm_x4(bf[nt][0], bf[nt][1], bf[nt][2], bf[nt][3],
                        bB + row * 128 + ((seg ^ lxor) << 4));
            }
            #pragma unroll
            for (int mt = 0; mt < 4; mt++)
                #pragma unroll
                for (int nt = 0; nt < 2; nt++) {
                    asm volatile(
                        "mma.sync.aligned.m16n8k16.row.col.f32.f16.f16.f32 "
                        "{%0,%1,%2,%3}, {%4,%5,%6,%7}, {%8,%9}, {%0,%1,%2,%3};\n"
                        : "+f"(acc[mt][2*nt][0]), "+f"(acc[mt][2*nt][1]),
                          "+f"(acc[mt][2*nt][2]), "+f"(acc[mt][2*nt][3])
                        : "r"(af[mt][0]), "r"(af[mt][1]), "r"(af[mt][2]), "r"(af[mt][3]),
                          "r"(bf[nt][0]), "r"(bf[nt][1]));
                    asm volatile(
                        "mma.sync.aligned.m16n8k16.row.col.f32.f16.f16.f32 "
                        "{%0,%1,%2,%3}, {%4,%5,%6,%7}, {%8,%9}, {%0,%1,%2,%3};\n"
                        : "+f"(acc[mt][2*nt+1][0]), "+f"(acc[mt][2*nt+1][1]),
                          "+f"(acc[mt][2*nt+1][2]), "+f"(acc[mt][2*nt+1][3])
                        : "r"(af[mt][0]), "r"(af[mt][1]), "r"(af[mt][2]), "r"(af[mt][3]),
                          "r"(bf[nt][2]), "r"(bf[nt][3]));
                }
        }
    }

    // ---- epilogue: per-column scale, fp32 stores ----
    const int l4r = lane >> 2;            // 0..7
    const int l4c = lane & 3;             // 0..3
    #pragma unroll
    for (int mt = 0; mt < 4; mt++) {
        const int r0 = bm * BM + wrow * 64 + mt * 16 + l4r;
        #pragma unroll
        for (int nt = 0; nt < 4; nt++) {
            const int n0 = bn * BN + wcol * 32 + nt * 8 + 2 * l4c;
            const float s0 = __ldg(g_scale + n0);
            const float s1 = __ldg(g_scale + n0 + 1);
            float2 v0 = make_float2(acc[mt][nt][0] * s0, acc[mt][nt][1] * s1);
            float2 v1 = make_float2(acc[mt][nt][2] * s0, acc[mt][nt][3] * s1);
            *reinterpret_cast<float2*>(C + (size_t)r0 * N_DIM + n0)       = v0;
            *reinterpret_cast<float2*>(C + (size_t)(r0 + 8) * N_DIM + n0) = v1;
        }
    }
}

// ---------------------------------------------------------------------------
extern "C" void kernel_launch(void* const* d_in, const int* in_sizes, int n_in,
                              void* d_out, int out_size) {
    (void)in_sizes; (void)n_in; (void)out_size;
    const float* x = (const float*)d_in[0];
    const float* w = (const float*)d_in[1];
    float* out = (float*)d_out;

    quant_w_kernel<<<N_DIM, 256>>>(w);
    conv_x_kernel<<<(unsigned)((size_t)M_DIM * K_DIM / 4 / 256), 256>>>(x);

    cudaFuncSetAttribute(gemm_f16_kernel,
                         cudaFuncAttributeMaxDynamicSharedMemorySize, SMEM_TOTAL);
    gemm_f16_kernel<<<(M_DIM / BM) * (N_DIM / BN), NTHREADS, SMEM_TOTAL>>>(out);
}

// round 7
// speedup vs baseline: 2.3749x; 1.0093x over previous
#include <cuda_runtime.h>
#include <cuda_fp16.h>
#include <cstdint>

// Problem dims (fixed by dataset)
#define M_DIM 8192
#define K_DIM 2048
#define N_DIM 8192

// GEMM tiling
#define BM 128
#define BN 256
#define BK 128                // halves per k-slice = 256 bytes per row
#define NKT (K_DIM / BK)      // 16
#define NSTAGE 2
#define NTHREADS 512
#define A_BYTES (BM * 256)    // 32768
#define B_BYTES (BN * 256)    // 65536
#define STAGE_BYTES (A_BYTES + B_BYTES)            // 98304
#define SMEM_TOTAL (NSTAGE * STAGE_BYTES)          // 196608

// Scratch (allocation-free rule: __device__ globals)
__device__ __half g_Xh[(size_t)M_DIM * K_DIM];
__device__ __half g_Wq[(size_t)N_DIM * K_DIM];
__device__ float  g_scale[N_DIM];

// ---------------------------------------------------------------------------
__device__ __forceinline__ uint32_t smem_u32(const void* p) {
    return (uint32_t)__cvta_generic_to_shared(p);
}
__device__ __forceinline__ void cp16(uint32_t dst, const void* src) {
    asm volatile("cp.async.cg.shared.global [%0], [%1], 16;\n" :: "r"(dst), "l"(src));
}
__device__ __forceinline__ void ldsm_x4(uint32_t& r0, uint32_t& r1, uint32_t& r2,
                                        uint32_t& r3, uint32_t addr) {
    asm volatile("ldmatrix.sync.aligned.m8n8.x4.shared.b16 {%0,%1,%2,%3}, [%4];"
                 : "=r"(r0), "=r"(r1), "=r"(r2), "=r"(r3) : "r"(addr));
}
__device__ __forceinline__ uint2 pack4_h(float a, float b, float c, float d) {
    __half2 p0 = __floats2half2_rn(a, b);
    __half2 p1 = __floats2half2_rn(c, d);
    uint2 r;
    r.x = *reinterpret_cast<uint32_t*>(&p0);
    r.y = *reinterpret_cast<uint32_t*>(&p1);
    return r;
}

// ---------------------------------------------------------------------------
// Kernel 1 (merged prep):
//   blocks [0, 8192): per-row weight quantization -> ternary fp16 + scale
//   blocks [8192, 8192+16384): x -> fp16 (4 floats / thread)
// ---------------------------------------------------------------------------
__global__ __launch_bounds__(256) void prep_kernel(const float* __restrict__ w,
                                                   const float* __restrict__ x) {
    const int tid = threadIdx.x;
    if (blockIdx.x >= N_DIM) {
        size_t i = (size_t)(blockIdx.x - N_DIM) * 256 + tid;
        float4 v = reinterpret_cast<const float4*>(x)[i];
        reinterpret_cast<uint2*>(g_Xh)[i] = pack4_h(v.x, v.y, v.z, v.w);
        return;
    }

    const int row  = blockIdx.x;
    const int lane = tid & 31, warp = tid >> 5;

    const float4* wr = reinterpret_cast<const float4*>(w + (size_t)row * K_DIM);
    float4 v0 = wr[tid];
    float4 v1 = wr[tid + 256];

    float s = fabsf(v0.x)+fabsf(v0.y)+fabsf(v0.z)+fabsf(v0.w)
            + fabsf(v1.x)+fabsf(v1.y)+fabsf(v1.z)+fabsf(v1.w);
    #pragma unroll
    for (int o = 16; o > 0; o >>= 1) s += __shfl_xor_sync(0xffffffffu, s, o);

    __shared__ float red[8];
    __shared__ float sc_sh;
    if (lane == 0) red[warp] = s;
    __syncthreads();
    if (tid == 0) {
        float tot = 0.f;
        #pragma unroll
        for (int i = 0; i < 8; i++) tot += red[i];
        sc_sh = fmaxf(tot * (1.0f / (float)K_DIM), 1e-5f);
    }
    __syncthreads();
    const float sc = sc_sh;

    float q[8];
    q[0]=__fdiv_rn(v0.x,sc); q[1]=__fdiv_rn(v0.y,sc); q[2]=__fdiv_rn(v0.z,sc); q[3]=__fdiv_rn(v0.w,sc);
    q[4]=__fdiv_rn(v1.x,sc); q[5]=__fdiv_rn(v1.y,sc); q[6]=__fdiv_rn(v1.z,sc); q[7]=__fdiv_rn(v1.w,sc);
    #pragma unroll
    for (int i = 0; i < 8; i++) q[i] = fminf(fmaxf(rintf(q[i]), -1.f), 1.f);

    uint2* dst = reinterpret_cast<uint2*>(g_Wq + (size_t)row * K_DIM);
    dst[tid]       = pack4_h(q[0], q[1], q[2], q[3]);
    dst[tid + 256] = pack4_h(q[4], q[5], q[6], q[7]);

    if (tid == 0) g_scale[row] = sc;
}

// ---------------------------------------------------------------------------
// Kernel 2: fp16 HMMA GEMM.  C[m,n] = scale[n] * sum_k Xh[m,k]*Wq[n,k]
// 128x256x128 tile, 512 thr (16 warps 2x8, warp tile 64x32), 2-stage cp.async,
// one __syncthreads per k-iter (16 iters).
// ---------------------------------------------------------------------------
__global__ __launch_bounds__(NTHREADS, 1) void gemm_f16_kernel(float* __restrict__ C) {
    extern __shared__ char smem[];
    const uint32_t sbase = smem_u32(smem);

    const int tid  = threadIdx.x;
    const int lane = tid & 31;
    const int warp = tid >> 5;
    const int wrow = warp >> 3;           // 0..1 (M, 64 each)
    const int wcol = warp & 7;            // 0..7 (N, 32 each)

    // CTA swizzle: GROUP=8 along M, walk all N inside a group (L2 reuse)
    const int GRID_N = N_DIM / BN;        // 32
    const int GROUP  = 8;
    const int nig    = GROUP * GRID_N;    // 256
    const int bid    = blockIdx.x;
    const int bm     = (bid / nig) * GROUP + (bid % nig) % GROUP;
    const int bn     = (bid % nig) / GROUP;

    const __half* Ag = g_Xh + (size_t)(bm * BM) * K_DIM;
    const __half* Bg = g_Wq + (size_t)(bn * BN) * K_DIM;

    // ldmatrix per-lane row/seg decomposition
    const int a_row = (lane & 7) + ((lane >> 3) & 1) * 8;   // 0..15
    const int a_sh  = lane >> 4;                            // k-seg half 0/1
    const int b_row = (lane & 7) + (lane >> 4) * 8;         // 0..15
    const int b_sh  = (lane >> 3) & 1;
    const int lxor  = lane & 7;

    float acc[4][4][4];
    #pragma unroll
    for (int a = 0; a < 4; a++)
        #pragma unroll
        for (int b = 0; b < 4; b++)
            #pragma unroll
            for (int c = 0; c < 4; c++) acc[a][b][c] = 0.f;

    // --- stage loader: 12 x 16B per thread (A:4, B:8); rows are 256B, 16 segs
    auto load_stage = [&](int kt, int s) {
        const uint32_t st = sbase + s * STAGE_BYTES;
        const int kof = kt * BK;
        #pragma unroll
        for (int i = 0; i < 4; i++) {                 // A: 2048 16B chunks
            int flat = tid + NTHREADS * i;
            int row = flat >> 4, seg = flat & 15;
            cp16(st + row * 256 + ((seg ^ (row & 7)) << 4),
                 Ag + (size_t)row * K_DIM + kof + seg * 8);
        }
        #pragma unroll
        for (int i = 0; i < 8; i++) {                 // B: 4096 16B chunks
            int flat = tid + NTHREADS * i;
            int row = flat >> 4, seg = flat & 15;
            cp16(st + A_BYTES + row * 256 + ((seg ^ (row & 7)) << 4),
                 Bg + (size_t)row * K_DIM + kof + seg * 8);
        }
        asm volatile("cp.async.commit_group;\n" ::: "memory");
    };

    // prologue
    load_stage(0, 0);

    #pragma unroll 1
    for (int kt = 0; kt < NKT; kt++) {
        asm volatile("cp.async.wait_group 0;\n" ::: "memory");  // stage kt resident
        __syncthreads();   // all warps done with compute(kt-1) -> its slot is free

        if (kt + 1 < NKT) load_stage(kt + 1, (kt + 1) & 1);     // overlaps compute(kt)

        const uint32_t aB = sbase + (kt & 1) * STAGE_BYTES;
        const uint32_t bB = aB + A_BYTES;

        #pragma unroll
        for (int ks = 0; ks < 8; ks++) {
            uint32_t af[4][4], bf[2][4];
            #pragma unroll
            for (int mt = 0; mt < 4; mt++) {
                const int row = wrow * 64 + mt * 16 + a_row;
                const int seg = 2 * ks + a_sh;
                ldsm_x4(af[mt][0], af[mt][1], af[mt][2], af[mt][3],
                        aB + row * 256 + ((seg ^ lxor) << 4));
            }
            #pragma unroll
            for (int nt = 0; nt < 2; nt++) {
                const int row = wcol * 32 + nt * 16 + b_row;
                const int seg = 2 * ks + b_sh;
                ldsm_x4(bf[nt][0], bf[nt][1], bf[nt][2], bf[nt][3],
                        bB + row * 256 + ((seg ^ lxor) << 4));
            }
            #pragma unroll
            for (int mt = 0; mt < 4; mt++)
                #pragma unroll
                for (int nt = 0; nt < 2; nt++) {
                    asm volatile(
                        "mma.sync.aligned.m16n8k16.row.col.f32.f16.f16.f32 "
                        "{%0,%1,%2,%3}, {%4,%5,%6,%7}, {%8,%9}, {%0,%1,%2,%3};\n"
                        : "+f"(acc[mt][2*nt][0]), "+f"(acc[mt][2*nt][1]),
                          "+f"(acc[mt][2*nt][2]), "+f"(acc[mt][2*nt][3])
                        : "r"(af[mt][0]), "r"(af[mt][1]), "r"(af[mt][2]), "r"(af[mt][3]),
                          "r"(bf[nt][0]), "r"(bf[nt][1]));
                    asm volatile(
                        "mma.sync.aligned.m16n8k16.row.col.f32.f16.f16.f32 "
                        "{%0,%1,%2,%3}, {%4,%5,%6,%7}, {%8,%9}, {%0,%1,%2,%3};\n"
                        : "+f"(acc[mt][2*nt+1][0]), "+f"(acc[mt][2*nt+1][1]),
                          "+f"(acc[mt][2*nt+1][2]), "+f"(acc[mt][2*nt+1][3])
                        : "r"(af[mt][0]), "r"(af[mt][1]), "r"(af[mt][2]), "r"(af[mt][3]),
                          "r"(bf[nt][2]), "r"(bf[nt][3]));
                }
        }
    }

    // ---- epilogue: per-column scale, fp32 stores ----
    const int l4r = lane >> 2;            // 0..7
    const int l4c = lane & 3;             // 0..3
    #pragma unroll
    for (int mt = 0; mt < 4; mt++) {
        const int r0 = bm * BM + wrow * 64 + mt * 16 + l4r;
        #pragma unroll
        for (int nt = 0; nt < 4; nt++) {
            const int n0 = bn * BN + wcol * 32 + nt * 8 + 2 * l4c;
            const float s0 = __ldg(g_scale + n0);
            const float s1 = __ldg(g_scale + n0 + 1);
            float2 v0 = make_float2(acc[mt][nt][0] * s0, acc[mt][nt][1] * s1);
            float2 v1 = make_float2(acc[mt][nt][2] * s0, acc[mt][nt][3] * s1);
            *reinterpret_cast<float2*>(C + (size_t)r0 * N_DIM + n0)       = v0;
            *reinterpret_cast<float2*>(C + (size_t)(r0 + 8) * N_DIM + n0) = v1;
        }
    }
}

// ---------------------------------------------------------------------------
extern "C" void kernel_launch(void* const* d_in, const int* in_sizes, int n_in,
                              void* d_out, int out_size) {
    (void)in_sizes; (void)n_in; (void)out_size;
    const float* x = (const float*)d_in[0];
    const float* w = (const float*)d_in[1];
    float* out = (float*)d_out;

    // merged prep: 8192 W-row blocks + 16384 x-conversion blocks
    prep_kernel<<<N_DIM + (unsigned)((size_t)M_DIM * K_DIM / 4 / 256), 256>>>(w, x);

    cudaFuncSetAttribute(gemm_f16_kernel,
                         cudaFuncAttributeMaxDynamicSharedMemorySize, SMEM_TOTAL);
    gemm_f16_kernel<<<(M_DIM / BM) * (N_DIM / BN), NTHREADS, SMEM_TOTAL>>>(out);
}

// round 8
// speedup vs baseline: 2.4763x; 1.0427x over previous
#include <cuda_runtime.h>
#include <cuda_fp16.h>
#include <cstdint>

// Problem dims (fixed by dataset)
#define M_DIM 8192
#define K_DIM 2048
#define N_DIM 8192

// GEMM tiling: 2 CTAs/SM
#define BM 128
#define BN 128
#define BK 64                 // halves per k-slice = 128 bytes per row
#define NKT (K_DIM / BK)      // 32
#define NSTAGE 3
#define NTHREADS 256
#define A_BYTES (BM * 128)    // 16384
#define B_BYTES (BN * 128)    // 16384
#define STAGE_BYTES (A_BYTES + B_BYTES)            // 32768
#define SMEM_TOTAL (NSTAGE * STAGE_BYTES)          // 98304 per CTA (x2 CTAs = 192KB/SM)

// Scratch (allocation-free rule: __device__ globals)
__device__ __half g_Xh[(size_t)M_DIM * K_DIM];
__device__ __half g_Wq[(size_t)N_DIM * K_DIM];
__device__ float  g_scale[N_DIM];

// ---------------------------------------------------------------------------
__device__ __forceinline__ uint32_t smem_u32(const void* p) {
    return (uint32_t)__cvta_generic_to_shared(p);
}
__device__ __forceinline__ void cp16(uint32_t dst, const void* src) {
    asm volatile("cp.async.cg.shared.global [%0], [%1], 16;\n" :: "r"(dst), "l"(src));
}
__device__ __forceinline__ void ldsm_x4(uint32_t& r0, uint32_t& r1, uint32_t& r2,
                                        uint32_t& r3, uint32_t addr) {
    asm volatile("ldmatrix.sync.aligned.m8n8.x4.shared.b16 {%0,%1,%2,%3}, [%4];"
                 : "=r"(r0), "=r"(r1), "=r"(r2), "=r"(r3) : "r"(addr));
}
__device__ __forceinline__ uint2 pack4_h(float a, float b, float c, float d) {
    __half2 p0 = __floats2half2_rn(a, b);
    __half2 p1 = __floats2half2_rn(c, d);
    uint2 r;
    r.x = *reinterpret_cast<uint32_t*>(&p0);
    r.y = *reinterpret_cast<uint32_t*>(&p1);
    return r;
}

// ---------------------------------------------------------------------------
// Kernel 1 (merged prep):
//   blocks [0, 8192): per-row weight quantization -> ternary fp16 + scale
//   blocks [8192, 8192+16384): x -> fp16 (4 floats / thread)
// ---------------------------------------------------------------------------
__global__ __launch_bounds__(256) void prep_kernel(const float* __restrict__ w,
                                                   const float* __restrict__ x) {
    const int tid = threadIdx.x;
    if (blockIdx.x >= N_DIM) {
        size_t i = (size_t)(blockIdx.x - N_DIM) * 256 + tid;
        float4 v = reinterpret_cast<const float4*>(x)[i];
        reinterpret_cast<uint2*>(g_Xh)[i] = pack4_h(v.x, v.y, v.z, v.w);
        return;
    }

    const int row  = blockIdx.x;
    const int lane = tid & 31, warp = tid >> 5;

    const float4* wr = reinterpret_cast<const float4*>(w + (size_t)row * K_DIM);
    float4 v0 = wr[tid];
    float4 v1 = wr[tid + 256];

    float s = fabsf(v0.x)+fabsf(v0.y)+fabsf(v0.z)+fabsf(v0.w)
            + fabsf(v1.x)+fabsf(v1.y)+fabsf(v1.z)+fabsf(v1.w);
    #pragma unroll
    for (int o = 16; o > 0; o >>= 1) s += __shfl_xor_sync(0xffffffffu, s, o);

    __shared__ float red[8];
    __shared__ float sc_sh;
    if (lane == 0) red[warp] = s;
    __syncthreads();
    if (tid == 0) {
        float tot = 0.f;
        #pragma unroll
        for (int i = 0; i < 8; i++) tot += red[i];
        sc_sh = fmaxf(tot * (1.0f / (float)K_DIM), 1e-5f);
    }
    __syncthreads();
    const float sc = sc_sh;

    float q[8];
    q[0]=__fdiv_rn(v0.x,sc); q[1]=__fdiv_rn(v0.y,sc); q[2]=__fdiv_rn(v0.z,sc); q[3]=__fdiv_rn(v0.w,sc);
    q[4]=__fdiv_rn(v1.x,sc); q[5]=__fdiv_rn(v1.y,sc); q[6]=__fdiv_rn(v1.z,sc); q[7]=__fdiv_rn(v1.w,sc);
    #pragma unroll
    for (int i = 0; i < 8; i++) q[i] = fminf(fmaxf(rintf(q[i]), -1.f), 1.f);

    uint2* dst = reinterpret_cast<uint2*>(g_Wq + (size_t)row * K_DIM);
    dst[tid]       = pack4_h(q[0], q[1], q[2], q[3]);
    dst[tid + 256] = pack4_h(q[4], q[5], q[6], q[7]);

    if (tid == 0) g_scale[row] = sc;
}

// ---------------------------------------------------------------------------
// Kernel 2: fp16 HMMA GEMM.  C[m,n] = scale[n] * sum_k Xh[m,k]*Wq[n,k]
// 128x128x64 tile, 256 thr (8 warps 2x4, warp tile 64x32), 3-stage cp.async,
// 2 CTAs per SM -> cross-CTA latency hiding.
// ---------------------------------------------------------------------------
__global__ __launch_bounds__(NTHREADS, 2) void gemm_f16_kernel(float* __restrict__ C) {
    extern __shared__ char smem[];
    const uint32_t sbase = smem_u32(smem);

    const int tid  = threadIdx.x;
    const int lane = tid & 31;
    const int warp = tid >> 5;
    const int wrow = warp >> 2;           // 0..1 (M, 64 each)
    const int wcol = warp & 3;            // 0..3 (N, 32 each)

    // CTA swizzle: GROUP=8 along M, walk all N inside a group (L2 reuse)
    const int GRID_N = N_DIM / BN;        // 64
    const int GROUP  = 8;
    const int nig    = GROUP * GRID_N;    // 512
    const int bid    = blockIdx.x;
    const int bm     = (bid / nig) * GROUP + (bid % nig) % GROUP;
    const int bn     = (bid % nig) / GROUP;

    const __half* Ag = g_Xh + (size_t)(bm * BM) * K_DIM;
    const __half* Bg = g_Wq + (size_t)(bn * BN) * K_DIM;

    // ldmatrix per-lane row/seg decomposition
    const int a_row = (lane & 7) + ((lane >> 3) & 1) * 8;   // 0..15
    const int a_sh  = lane >> 4;                            // k-seg half 0/1
    const int b_row = (lane & 7) + (lane >> 4) * 8;         // 0..15
    const int b_sh  = (lane >> 3) & 1;
    const int lxor  = lane & 7;

    float acc[4][4][4];
    #pragma unroll
    for (int a = 0; a < 4; a++)
        #pragma unroll
        for (int b = 0; b < 4; b++)
            #pragma unroll
            for (int c = 0; c < 4; c++) acc[a][b][c] = 0.f;

    // --- stage loader: 8 x 16B per thread (A:4, B:4); rows 128B, 8 segs ---
    auto load_stage = [&](int kt, int s) {
        const uint32_t st = sbase + s * STAGE_BYTES;
        const int kof = kt * BK;
        #pragma unroll
        for (int i = 0; i < 4; i++) {                 // A: 1024 16B chunks
            int flat = tid + NTHREADS * i;
            int row = flat >> 3, seg = flat & 7;
            cp16(st + row * 128 + ((seg ^ (row & 7)) << 4),
                 Ag + (size_t)row * K_DIM + kof + seg * 8);
        }
        #pragma unroll
        for (int i = 0; i < 4; i++) {                 // B: 1024 16B chunks
            int flat = tid + NTHREADS * i;
            int row = flat >> 3, seg = flat & 7;
            cp16(st + A_BYTES + row * 128 + ((seg ^ (row & 7)) << 4),
                 Bg + (size_t)row * K_DIM + kof + seg * 8);
        }
    };

    // prologue: stages 0..NSTAGE-2
    #pragma unroll
    for (int j = 0; j < NSTAGE - 1; j++) {
        load_stage(j, j);
        asm volatile("cp.async.commit_group;\n" ::: "memory");
    }

    #pragma unroll 1
    for (int kt = 0; kt < NKT; kt++) {
        asm volatile("cp.async.wait_group %0;\n" :: "n"(NSTAGE - 2) : "memory");
        __syncthreads();   // stage kt visible; slot of (kt-1) free for reuse

        const int j = kt + NSTAGE - 1;
        if (j < NKT) load_stage(j, j % NSTAGE);
        asm volatile("cp.async.commit_group;\n" ::: "memory");   // empty group in tail

        const uint32_t aB = sbase + (kt % NSTAGE) * STAGE_BYTES;
        const uint32_t bB = aB + A_BYTES;

        #pragma unroll
        for (int ks = 0; ks < 4; ks++) {
            uint32_t af[4][4], bf[2][4];
            #pragma unroll
            for (int mt = 0; mt < 4; mt++) {
                const int row = wrow * 64 + mt * 16 + a_row;
                const int seg = 2 * ks + a_sh;
                ldsm_x4(af[mt][0], af[mt][1], af[mt][2], af[mt][3],
                        aB + row * 128 + ((seg ^ lxor) << 4));
            }
            #pragma unroll
            for (int nt = 0; nt < 2; nt++) {
                const int row = wcol * 32 + nt * 16 + b_row;
                const int seg = 2 * ks + b_sh;
                ldsm_x4(bf[nt][0], bf[nt][1], bf[nt][2], bf[nt][3],
                        bB + row * 128 + ((seg ^ lxor) << 4));
            }
            #pragma unroll
            for (int mt = 0; mt < 4; mt++)
                #pragma unroll
                for (int nt = 0; nt < 2; nt++) {
                    asm volatile(
                        "mma.sync.aligned.m16n8k16.row.col.f32.f16.f16.f32 "
                        "{%0,%1,%2,%3}, {%4,%5,%6,%7}, {%8,%9}, {%0,%1,%2,%3};\n"
                        : "+f"(acc[mt][2*nt][0]), "+f"(acc[mt][2*nt][1]),
                          "+f"(acc[mt][2*nt][2]), "+f"(acc[mt][2*nt][3])
                        : "r"(af[mt][0]), "r"(af[mt][1]), "r"(af[mt][2]), "r"(af[mt][3]),
                          "r"(bf[nt][0]), "r"(bf[nt][1]));
                    asm volatile(
                        "mma.sync.aligned.m16n8k16.row.col.f32.f16.f16.f32 "
                        "{%0,%1,%2,%3}, {%4,%5,%6,%7}, {%8,%9}, {%0,%1,%2,%3};\n"
                        : "+f"(acc[mt][2*nt+1][0]), "+f"(acc[mt][2*nt+1][1]),
                          "+f"(acc[mt][2*nt+1][2]), "+f"(acc[mt][2*nt+1][3])
                        : "r"(af[mt][0]), "r"(af[mt][1]), "r"(af[mt][2]), "r"(af[mt][3]),
                          "r"(bf[nt][2]), "r"(bf[nt][3]));
                }
        }
    }

    // ---- epilogue: per-column scale, fp32 stores ----
    const int l4r = lane >> 2;            // 0..7
    const int l4c = lane & 3;             // 0..3
    #pragma unroll
    for (int mt = 0; mt < 4; mt++) {
        const int r0 = bm * BM + wrow * 64 + mt * 16 + l4r;
        #pragma unroll
        for (int nt = 0; nt < 4; nt++) {
            const int n0 = bn * BN + wcol * 32 + nt * 8 + 2 * l4c;
            const float s0 = __ldg(g_scale + n0);
            const float s1 = __ldg(g_scale + n0 + 1);
            float2 v0 = make_float2(acc[mt][nt][0] * s0, acc[mt][nt][1] * s1);
            float2 v1 = make_float2(acc[mt][nt][2] * s0, acc[mt][nt][3] * s1);
            *reinterpret_cast<float2*>(C + (size_t)r0 * N_DIM + n0)       = v0;
            *reinterpret_cast<float2*>(C + (size_t)(r0 + 8) * N_DIM + n0) = v1;
        }
    }
}

// ---------------------------------------------------------------------------
extern "C" void kernel_launch(void* const* d_in, const int* in_sizes, int n_in,
                              void* d_out, int out_size) {
    (void)in_sizes; (void)n_in; (void)out_size;
    const float* x = (const float*)d_in[0];
    const float* w = (const float*)d_in[1];
    float* out = (float*)d_out;

    // merged prep: 8192 W-row blocks + 16384 x-conversion blocks
    prep_kernel<<<N_DIM + (unsigned)((size_t)M_DIM * K_DIM / 4 / 256), 256>>>(w, x);

    cudaFuncSetAttribute(gemm_f16_kernel,
                         cudaFuncAttributeMaxDynamicSharedMemorySize, SMEM_TOTAL);
    gemm_f16_kernel<<<(M_DIM / BM) * (N_DIM / BN), NTHREADS, SMEM_TOTAL>>>(out);
}